// round 9
// baseline (speedup 1.0000x reference)
#include <cuda_runtime.h>
#include <cstdint>

// preds/target = [B=8, C=21, H=512, W=512] fp32, contiguous.
// R9: dynamic work-stealing over 21504 units of 512 float4 (128/slab, class
// uniform per unit). Per-block smem per-class accumulator [21][3] -> class
// changes cost nothing; global atomics once per block at the end. Work index
// double-buffered: next unit pulled at top of body so ATOMG latency hides
// behind the load loop; ONE barrier per unit. Packed warp reduce (5 shfls).
// Fused last-block finalize + full self-reset (graph-replay safe).

#define NCLS 21
#define UNIT_V4 512                           // float4 per unit
#define UNITS_PER_SLAB 128                    // 65536 / 512
#define TOTAL_UNITS (168 * UNITS_PER_SLAB)    // 21504
#define THREADS 256
#define ITERS (UNIT_V4 / THREADS)             // 2
#define GRID_BLOCKS 1184                      // 148 SMs * 8 blocks (one wave)

// g_cnt layout: [cls*3 + 0]=pred_sum, +1=target_sum, +2=intersection
__device__ int g_cnt[NCLS * 3];
__device__ unsigned int g_next;               // work-stealing cursor
__device__ unsigned int g_done;               // completion count

__global__ __launch_bounds__(THREADS, 8) void jidx_fused_kernel(
    const float4* __restrict__ preds4,
    const float4* __restrict__ targ4,
    float* __restrict__ out)
{
    __shared__ int s_acc[NCLS * 3];
    __shared__ unsigned int s_u[2];
    __shared__ int s_last;

    for (int i = threadIdx.x; i < NCLS * 3; i += THREADS) s_acc[i] = 0;
    if (threadIdx.x == 0) s_u[0] = atomicAdd(&g_next, 1u);
    __syncthreads();

    for (int k = 0; ; ++k) {
        const unsigned int u = s_u[k & 1];
        if (u >= TOTAL_UNITS) break;                 // uniform exit
        // Prefetch next unit index; ATOMG latency hides behind the loads.
        if (threadIdx.x == 0) s_u[(k + 1) & 1] = atomicAdd(&g_next, 1u);

        const int cls = (int)((u >> 7) % NCLS);      // slab = u / 128
        const size_t base = (size_t)u * UNIT_V4 + threadIdx.x;

        // packed = ps | ts<<10 | inter<<20 ; per-warp totals <= 256 < 1023.
        int packed = 0;
        #pragma unroll
        for (int j = 0; j < ITERS; ++j) {
            float4 p = __ldcs(preds4 + base + j * THREADS);
            float4 t = __ldcs(targ4  + base + j * THREADS);
            int p0 = p.x >= 0.5f, p1 = p.y >= 0.5f, p2 = p.z >= 0.5f, p3 = p.w >= 0.5f;
            int t0 = t.x == 1.0f, t1 = t.y == 1.0f, t2 = t.z == 1.0f, t3 = t.w == 1.0f;
            int ps = p0 + p1 + p2 + p3;
            int ts = t0 + t1 + t2 + t3;
            int in = (p0 & t0) + (p1 & t1) + (p2 & t2) + (p3 & t3);
            packed += ps + (ts << 10) + (in << 20);
        }

        #pragma unroll
        for (int o = 16; o > 0; o >>= 1)
            packed += __shfl_down_sync(0xffffffffu, packed, o);

        if ((threadIdx.x & 31) == 0) {
            atomicAdd(&s_acc[cls * 3 + 0],  packed        & 1023);
            atomicAdd(&s_acc[cls * 3 + 1], (packed >> 10) & 1023);
            atomicAdd(&s_acc[cls * 3 + 2], (packed >> 20) & 1023);
        }
        __syncthreads();   // orders next s_u write -> read; nothing else needed
    }

    // Drain block totals to global (once per block, 63 atomics).
    __syncthreads();
    for (int i = threadIdx.x; i < NCLS * 3; i += THREADS)
        atomicAdd(&g_cnt[i], s_acc[i]);

    // Completion protocol: one arrival per block.
    if (threadIdx.x == 0) {
        __threadfence();                 // publish counts before done++
        unsigned int t = atomicAdd(&g_done, 1u);
        s_last = (t == (unsigned int)(GRID_BLOCKS - 1));
    }
    __syncthreads();

    if (s_last) {
        __threadfence();                 // acquire all published counts
        if (threadIdx.x < NCLS) {
            int i = threadIdx.x;
            float ps    = (float)g_cnt[i * 3 + 0];
            float ts    = (float)g_cnt[i * 3 + 1];
            float inter = (float)g_cnt[i * 3 + 2];
            float uni = ps + ts - inter;
            out[i] = (uni == 0.0f) ? __int_as_float(0x7fc00000)  // NaN
                                   : inter / fmaxf(uni, 1.0f);
            // self-reset for next graph replay
            g_cnt[i * 3 + 0] = 0;
            g_cnt[i * 3 + 1] = 0;
            g_cnt[i * 3 + 2] = 0;
        }
        if (threadIdx.x == 0) { g_next = 0u; g_done = 0u; }
    }
}

extern "C" void kernel_launch(void* const* d_in, const int* in_sizes, int n_in,
                              void* d_out, int out_size) {
    const float4* preds4 = (const float4*)d_in[0];
    const float4* targ4  = (const float4*)d_in[1];
    float* out = (float*)d_out;

    jidx_fused_kernel<<<GRID_BLOCKS, THREADS>>>(preds4, targ4, out);
}

// round 10
// speedup vs baseline: 1.0016x; 1.0016x over previous
#include <cuda_runtime.h>
#include <cstdint>

// preds/target = [B=8, C=21, H=512, W=512] fp32, contiguous.
// R10 = R8's proven unit size (1024 float4, 10752 units, class uniform per
// unit) + R9's cheap per-unit machinery: prefetched work cursor (ATOMG
// hidden behind loads, ONE barrier per unit), packed 32-bit warp reduce
// (per-warp per-unit <= 512 elems < 1023 -> 10-bit fields safe), smem
// per-class accumulator (global atomics once per block). Fused last-block
// finalize + full self-reset (graph-replay safe).

#define NCLS 21
#define UNIT_V4 1024                          // float4 per unit
#define UNITS_PER_SLAB 64                     // 65536 / 1024
#define TOTAL_UNITS (168 * UNITS_PER_SLAB)    // 10752
#define THREADS 256
#define ITERS (UNIT_V4 / THREADS)             // 4
#define GRID_BLOCKS 1184                      // 148 SMs * 8 blocks (one wave)

// g_cnt layout: [cls*3 + 0]=pred_sum, +1=target_sum, +2=intersection
__device__ int g_cnt[NCLS * 3];
__device__ unsigned int g_next;               // work-stealing cursor
__device__ unsigned int g_done;               // completion count

__global__ __launch_bounds__(THREADS, 8) void jidx_fused_kernel(
    const float4* __restrict__ preds4,
    const float4* __restrict__ targ4,
    float* __restrict__ out)
{
    __shared__ int s_acc[NCLS * 3];
    __shared__ unsigned int s_u[2];
    __shared__ int s_last;

    for (int i = threadIdx.x; i < NCLS * 3; i += THREADS) s_acc[i] = 0;
    if (threadIdx.x == 0) s_u[0] = atomicAdd(&g_next, 1u);
    __syncthreads();

    for (int k = 0; ; ++k) {
        const unsigned int u = s_u[k & 1];
        if (u >= TOTAL_UNITS) break;                 // uniform exit
        // Prefetch next unit index; ATOMG latency hides behind the loads.
        if (threadIdx.x == 0) s_u[(k + 1) & 1] = atomicAdd(&g_next, 1u);

        const int cls = (int)((u >> 6) % NCLS);      // slab = u / 64
        const size_t base = (size_t)u * UNIT_V4 + threadIdx.x;

        // packed = ps | ts<<10 | inter<<20 ; per-warp totals <= 512 < 1023.
        int packed = 0;
        #pragma unroll
        for (int j = 0; j < ITERS; ++j) {
            float4 p = __ldcs(preds4 + base + j * THREADS);
            float4 t = __ldcs(targ4  + base + j * THREADS);
            int p0 = p.x >= 0.5f, p1 = p.y >= 0.5f, p2 = p.z >= 0.5f, p3 = p.w >= 0.5f;
            int t0 = t.x == 1.0f, t1 = t.y == 1.0f, t2 = t.z == 1.0f, t3 = t.w == 1.0f;
            int ps = p0 + p1 + p2 + p3;
            int ts = t0 + t1 + t2 + t3;
            int in = (p0 & t0) + (p1 & t1) + (p2 & t2) + (p3 & t3);
            packed += ps + (ts << 10) + (in << 20);
        }

        #pragma unroll
        for (int o = 16; o > 0; o >>= 1)
            packed += __shfl_down_sync(0xffffffffu, packed, o);

        if ((threadIdx.x & 31) == 0) {
            atomicAdd(&s_acc[cls * 3 + 0],  packed        & 1023);
            atomicAdd(&s_acc[cls * 3 + 1], (packed >> 10) & 1023);
            atomicAdd(&s_acc[cls * 3 + 2], (packed >> 20) & 1023);
        }
        __syncthreads();   // publish next s_u; orders smem acc too
    }

    // Drain block totals to global (once per block, 63 atomics).
    __syncthreads();
    for (int i = threadIdx.x; i < NCLS * 3; i += THREADS)
        atomicAdd(&g_cnt[i], s_acc[i]);

    // Completion protocol: one arrival per block.
    if (threadIdx.x == 0) {
        __threadfence();                 // publish counts before done++
        unsigned int t = atomicAdd(&g_done, 1u);
        s_last = (t == (unsigned int)(GRID_BLOCKS - 1));
    }
    __syncthreads();

    if (s_last) {
        __threadfence();                 // acquire all published counts
        if (threadIdx.x < NCLS) {
            int i = threadIdx.x;
            float ps    = (float)g_cnt[i * 3 + 0];
            float ts    = (float)g_cnt[i * 3 + 1];
            float inter = (float)g_cnt[i * 3 + 2];
            float uni = ps + ts - inter;
            out[i] = (uni == 0.0f) ? __int_as_float(0x7fc00000)  // NaN
                                   : inter / fmaxf(uni, 1.0f);
            // self-reset for next graph replay
            g_cnt[i * 3 + 0] = 0;
            g_cnt[i * 3 + 1] = 0;
            g_cnt[i * 3 + 2] = 0;
        }
        if (threadIdx.x == 0) { g_next = 0u; g_done = 0u; }
    }
}

extern "C" void kernel_launch(void* const* d_in, const int* in_sizes, int n_in,
                              void* d_out, int out_size) {
    const float4* preds4 = (const float4*)d_in[0];
    const float4* targ4  = (const float4*)d_in[1];
    float* out = (float*)d_out;

    jidx_fused_kernel<<<GRID_BLOCKS, THREADS>>>(preds4, targ4, out);
}